// round 9
// baseline (speedup 1.0000x reference)
#include <cuda_runtime.h>
#include <cstdint>

typedef unsigned long long ull;

#define NB      16
#define NENT    100000
#define NTILES  3125           // NENT / 32
#define GRID    592            // 4 blocks per SM (148 SMs)
#define TPB     128            // 4 warps = 2 pairs
#define NW      4
#define NPAIR   2
#define ROWF4   33             // float4 per staged row (32 data + 1 pad)
#define PAIR_F4 (32 * ROWF4)   // 1056 float4 per pair tile
// dynamic smem: h 8192 B + 2 pairs * 16896 B = 41984 B  (x4 blocks = 167936 <= 228KB)
#define SMEM_BYTES (8192 + NPAIR * PAIR_F4 * 16)

// ---------------- device scratch (allocation-free) ----------------
__device__ float    g_part[NB * GRID];
__device__ unsigned g_ctr;     // tile work queue
__device__ unsigned g_done;    // grid barrier epoch counter (monotonic)

// ---------------- packed f32x2 helpers (sm_103a) ----------------
__device__ __forceinline__ ull add2(ull a, ull b) {
    ull r; asm("add.rn.f32x2 %0,%1,%2;" : "=l"(r) : "l"(a), "l"(b)); return r;
}
__device__ __forceinline__ ull mul2(ull a, ull b) {
    ull r; asm("mul.rn.f32x2 %0,%1,%2;" : "=l"(r) : "l"(a), "l"(b)); return r;
}
__device__ __forceinline__ ull abs2(ull a) { return a & 0x7FFFFFFF7FFFFFFFull; }
__device__ __forceinline__ ull pk2(float a, float b) {
    ull r; asm("mov.b64 %0,{%1,%2};" : "=l"(r) : "f"(a), "f"(b)); return r;
}
__device__ __forceinline__ float2 upk(ull a) {
    float2 f; asm("mov.b64 {%0,%1},%2;" : "=f"(f.x), "=f"(f.y) : "l"(a)); return f;
}
__device__ __forceinline__ float wsum(float v) {
    #pragma unroll
    for (int o = 16; o; o >>= 1) v += __shfl_xor_sync(0xffffffffu, v, o);
    return v;
}
__device__ __forceinline__ unsigned sm_u32(const void* p) {
    unsigned a;
    asm("{ .reg .u64 t; cvta.to.shared.u64 t, %1; cvt.u32.u64 %0, t; }" : "=r"(a) : "l"(p));
    return a;
}
__device__ __forceinline__ void cpa16(unsigned dst, const void* src) {
    asm volatile("cp.async.cg.shared.global [%0], [%1], 16;" :: "r"(dst), "l"(src));
}
__device__ __forceinline__ void barp(int id) {   // pair barrier: 64 threads
    asm volatile("bar.sync %0, 64;" :: "r"(id) : "memory");
}

// =============== single fused kernel ===============
__global__ void __launch_bounds__(TPB, 4)
k_fused(const float* __restrict__ ent, const float* __restrict__ relemb,
        const int* __restrict__ e1w, const int* __restrict__ relw,
        float* __restrict__ out) {
    extern __shared__ float smf[];
    float*      hs   = smf;                           // 16*128 floats, persistent
    ulonglong2* hs2  = (ulonglong2*)smf;              // [16][32] 16B chunks

    int tid = threadIdx.x, w = tid >> 5, l = tid & 31;
    int p = w >> 1, role = w & 1;                     // pair id, b-half role

    float4*     xs4  = (float4*)(smf + 2048) + p * PAIR_F4;
    unsigned    xw_u = sm_u32(xs4);
    const ulonglong2* myrow2 = (const ulonglong2*)(xs4 + l * ROWF4);  // lane's row

    __shared__ unsigned tsl[NPAIR];
    __shared__ float    sp[NW][8];
    __shared__ float    sinv_s[NB];

    // ---- index width detection (int64 => high words zero) ----
    int odd  = e1w[1] | e1w[3] | e1w[5] | e1w[7] | e1w[9] | e1w[11] | e1w[13] | e1w[15];
    int is64 = (odd == 0);

    // ---- build h = norm(ent[e1[b]]) + norm(rel[rel[b]]) ----
    for (int b = w; b < NB; b += NW) {
        long long ei, ri;
        if (is64) { ei = ((const long long*)e1w)[b]; ri = ((const long long*)relw)[b]; }
        else      { ei = (long long)e1w[b];          ri = (long long)relw[b]; }
        float4 a = ((const float4*)ent)[(size_t)ei * 32 + l];
        float sa = wsum(fmaf(a.x, a.x, fmaf(a.y, a.y, fmaf(a.z, a.z, a.w * a.w))));
        float ia = rsqrtf(fmaxf(sa, 1e-24f));
        float4 c = ((const float4*)relemb)[(size_t)ri * 32 + l];
        float sc = wsum(fmaf(c.x, c.x, fmaf(c.y, c.y, fmaf(c.z, c.z, c.w * c.w))));
        float ic = rsqrtf(fmaxf(sc, 1e-24f));
        float4 h;
        h.x = fmaf(a.x, ia, c.x * ic);
        h.y = fmaf(a.y, ia, c.y * ic);
        h.z = fmaf(a.z, ia, c.z * ic);
        h.w = fmaf(a.w, ia, c.w * ic);
        ((float4*)hs)[b * 32 + l] = h;
    }
    __syncthreads();

    float es[8];
    #pragma unroll
    for (int j = 0; j < 8; j++) es[j] = 0.0f;
    const int bq  = role * 8;                          // my b rows: bq..bq+7
    const int bid = p + 1;                             // named barrier id
    const ulonglong2* hbA = hs2 + (bq + 0) * 32;       // b rows bq..bq+3
    const ulonglong2* hbB = hs2 + (bq + 4) * 32;       // b rows bq+4..bq+7

    // ---- initial tile fetch (role-0 warp publishes to the pair) ----
    if (role == 0 && l == 0) tsl[p] = atomicAdd(&g_ctr, 1u);
    barp(bid);
    unsigned t = tsl[p];

    // =============== phase 1: dist -> exp -> store ===============
    while (t < (unsigned)NTILES) {
        int base = (int)t * 32;

        // stage my role's 16 rows (coalesced 512B rows; lane l copies 16B chunk l)
        {
            const char* src = (const char*)ent + ((size_t)base + role * 16) * 512 + l * 16;
            unsigned    dst = xw_u + (unsigned)((role * 16) * ROWF4 + l) * 16;
            #pragma unroll
            for (int k = 0; k < 16; k++)
                cpa16(dst + k * (ROWF4 * 16), src + (size_t)k * 512);
            asm volatile("cp.async.commit_group;");
        }
        if (role == 0 && l == 0) tsl[p] = atomicAdd(&g_ctr, 1u);
        asm volatile("cp.async.wait_group 0;");
        barp(bid);                                     // both halves staged + tsl visible
        unsigned tn = tsl[p];

        // ---- sumsq + in-place prescale of my role's 16 rows (2 lanes/row) ----
        {
            int rloc = role * 16 + (l >> 1), half = l & 1;
            ulonglong2* rp = (ulonglong2*)(xs4 + rloc * ROWF4) + half;  // stride 2
            float s0 = 0.f, s1 = 0.f;
            #pragma unroll
            for (int k = 0; k < 16; k += 2) {
                float4 v0 = *(const float4*)(rp + 2 * k);
                float4 v1 = *(const float4*)(rp + 2 * (k + 1));
                s0 = fmaf(v0.x, v0.x, fmaf(v0.y, v0.y, fmaf(v0.z, v0.z, fmaf(v0.w, v0.w, s0))));
                s1 = fmaf(v1.x, v1.x, fmaf(v1.y, v1.y, fmaf(v1.z, v1.z, fmaf(v1.w, v1.w, s1))));
            }
            float ss = s0 + s1;
            ss += __shfl_xor_sync(0xffffffffu, ss, 1);
            float inv = -rsqrtf(fmaxf(ss, 1e-24f));    // xn = -x * rsqrt(ss)
            ull ii = pk2(inv, inv);
            #pragma unroll
            for (int k = 0; k < 16; k++) {
                ulonglong2 u = rp[2 * k];
                u.x = mul2(u.x, ii);
                u.y = mul2(u.y, ii);
                rp[2 * k] = u;
            }
        }
        barp(bid);                                     // all rows prescaled

        // ---- inner loop: software-pipelined h + x registers ----
        ull acc[8];
        #pragma unroll
        for (int j = 0; j < 8; j++) acc[j] = 0ull;

        ull hA[8], hB[8], xc0, xc1;
        {
            ulonglong2 xx = myrow2[0];
            xc0 = xx.x; xc1 = xx.y;
            #pragma unroll
            for (int j = 0; j < 4; j++) {
                ulonglong2 ha = hbA[j * 32];
                ulonglong2 hb = hbB[j * 32];
                hA[2*j] = ha.x; hA[2*j+1] = ha.y;
                hB[2*j] = hb.x; hB[2*j+1] = hb.y;
            }
        }

        #pragma unroll 4
        for (int c = 0; c < 32; c++) {
            int cn = (c + 1) & 31;                     // wrap: last-iter loads are dead
            ull x0 = xc0, x1 = xc1;
            { ulonglong2 xx = myrow2[cn]; xc0 = xx.x; xc1 = xx.y; }

            // half A math (b bq..bq+3), then reload hA for chunk c+1
            #pragma unroll
            for (int j = 0; j < 4; j++) {
                acc[j] = add2(acc[j], abs2(add2(hA[2*j],   x0)));
                acc[j] = add2(acc[j], abs2(add2(hA[2*j+1], x1)));
            }
            #pragma unroll
            for (int j = 0; j < 4; j++) {
                ulonglong2 hh = hbA[j * 32 + cn];
                hA[2*j] = hh.x; hA[2*j+1] = hh.y;
            }

            // half B math (b bq+4..bq+7), then reload hB for chunk c+1
            #pragma unroll
            for (int j = 0; j < 4; j++) {
                acc[4+j] = add2(acc[4+j], abs2(add2(hB[2*j],   x0)));
                acc[4+j] = add2(acc[4+j], abs2(add2(hB[2*j+1], x1)));
            }
            #pragma unroll
            for (int j = 0; j < 4; j++) {
                ulonglong2 hh = hbB[j * 32 + cn];
                hB[2*j] = hh.x; hB[2*j+1] = hh.y;
            }
        }

        // exp + store (dist <= ~34: no max pass), coalesced per b
        {
            float* outp = out + (size_t)bq * NENT + base + l;
            #pragma unroll
            for (int j = 0; j < 8; j++) {
                float2 f = upk(acc[j]);
                float e = __expf(f.x + f.y);
                outp[(size_t)j * NENT] = e;
                es[j] += e;
            }
        }

        barp(bid);                                     // pair done reading staging
        t = tn;
    }

    // ---- warp -> block row sums ----
    #pragma unroll
    for (int j = 0; j < 8; j++) {
        float s = wsum(es[j]);
        if (l == 0) sp[w][j] = s;
    }
    __syncthreads();
    if (tid < NB) {
        int b = tid, rr = b >> 3, j = b & 7;
        float s = sp[rr][j] + sp[2 + rr][j];           // pairs 0 and 1, role rr
        g_part[b * GRID + blockIdx.x] = s;
    }

    // =============== grid-wide barrier (all 592 blocks co-resident) ===============
    __syncthreads();
    if (tid == 0) {
        __threadfence();
        unsigned old = atomicAdd(&g_done, 1u);
        unsigned target = (old / GRID + 1u) * GRID;
        if (old % GRID == GRID - 1u) g_ctr = 0u;       // reset queue for next replay
        unsigned d;
        do {
            asm volatile("ld.global.acquire.gpu.u32 %0, [%1];" : "=r"(d) : "l"(&g_done));
        } while (d < target);
    }
    __syncthreads();

    // ---- reduce partials -> 1/sum per row ----
    for (int b = w; b < NB; b += NW) {
        float s = 0.f;
        for (int i = l; i < GRID; i += 32) s += g_part[b * GRID + i];
        s = wsum(s);
        if (l == 0) sinv_s[b] = 1.0f / s;
    }
    __syncthreads();

    // =============== phase 2: normalize in place (L2-hot) ===============
    {
        const int total4 = NB * NENT / 4;              // 400000
        const int chunk  = (total4 + GRID - 1) / GRID; // 676
        int start = blockIdx.x * chunk;
        int end   = min(start + chunk, total4);
        float4* o4 = (float4*)out;
        for (int i = start + tid; i < end; i += TPB) {
            int b = i / (NENT / 4);
            float iv = sinv_s[b];
            float4 v = o4[i];
            v.x *= iv; v.y *= iv; v.z *= iv; v.w *= iv;
            o4[i] = v;
        }
    }
}

// ---------------- launch ----------------
extern "C" void kernel_launch(void* const* d_in, const int* in_sizes, int n_in,
                              void* d_out, int out_size) {
    const int*   e1     = (const int*)d_in[0];
    const int*   rel    = (const int*)d_in[1];
    // d_in[2]=X, d_in[3]=A unused by the forward pass
    const float* ent    = (const float*)d_in[4];
    const float* relemb = (const float*)d_in[5];
    float* out = (float*)d_out;

    cudaFuncSetAttribute(k_fused, cudaFuncAttributeMaxDynamicSharedMemorySize, SMEM_BYTES);
    k_fused<<<GRID, TPB, SMEM_BYTES>>>(ent, relemb, e1, rel, out);
    (void)in_sizes; (void)n_in; (void)out_size;
}

// round 10
// speedup vs baseline: 1.0033x; 1.0033x over previous
#include <cuda_runtime.h>
#include <cstdint>

typedef unsigned long long ull;

#define NB      16
#define NENT    100000
#define NTILES  3125           // NENT / 32
#define GRID    296            // 2 blocks per SM (148 SMs) -- all co-resident
#define TPB     192            // 6 warps, each fully independent
#define NW      6
#define ROWF4   33             // float4 per staged row (32 data + 1 pad -> conflict-free)
#define WARP_F4 (32 * ROWF4)   // 1056 float4 per warp tile
// dynamic smem: h 8192 B + 6 warps * 16896 B = 109568 B (x2 blocks = 219136 <= 228KB)
#define SMEM_BYTES (8192 + NW * WARP_F4 * 16)

// ---------------- device scratch (allocation-free) ----------------
__device__ float    g_part[NB * GRID];
__device__ unsigned g_ctr;     // tile work queue
__device__ unsigned g_done;    // grid barrier epoch counter (monotonic)

// ---------------- packed f32x2 helpers (sm_103a) ----------------
__device__ __forceinline__ ull add2(ull a, ull b) {
    ull r; asm("add.rn.f32x2 %0,%1,%2;" : "=l"(r) : "l"(a), "l"(b)); return r;
}
__device__ __forceinline__ ull mul2(ull a, ull b) {
    ull r; asm("mul.rn.f32x2 %0,%1,%2;" : "=l"(r) : "l"(a), "l"(b)); return r;
}
__device__ __forceinline__ ull abs2(ull a) { return a & 0x7FFFFFFF7FFFFFFFull; }
__device__ __forceinline__ ull pk2(float a, float b) {
    ull r; asm("mov.b64 %0,{%1,%2};" : "=l"(r) : "f"(a), "f"(b)); return r;
}
__device__ __forceinline__ float2 upk(ull a) {
    float2 f; asm("mov.b64 {%0,%1},%2;" : "=f"(f.x), "=f"(f.y) : "l"(a)); return f;
}
__device__ __forceinline__ float wsum(float v) {
    #pragma unroll
    for (int o = 16; o; o >>= 1) v += __shfl_xor_sync(0xffffffffu, v, o);
    return v;
}
__device__ __forceinline__ unsigned sm_u32(const void* p) {
    unsigned a;
    asm("{ .reg .u64 t; cvta.to.shared.u64 t, %1; cvt.u32.u64 %0, t; }" : "=r"(a) : "l"(p));
    return a;
}
__device__ __forceinline__ void cpa16(unsigned dst, const void* src) {
    asm volatile("cp.async.cg.shared.global [%0], [%1], 16;" :: "r"(dst), "l"(src));
}

// =============== single fused kernel ===============
__global__ void __launch_bounds__(TPB, 2)
k_fused(const float* __restrict__ ent, const float* __restrict__ relemb,
        const int* __restrict__ e1w, const int* __restrict__ relw,
        float* __restrict__ out) {
    extern __shared__ float smf[];
    float*      hs  = smf;                             // 16*128 floats, persistent
    ulonglong2* hs2 = (ulonglong2*)smf;                // [16][32] 16B chunks

    int tid = threadIdx.x, w = tid >> 5, l = tid & 31;

    float4*     xs4  = (float4*)(smf + 2048) + w * WARP_F4;  // this warp's staging
    unsigned    xw_u = sm_u32(xs4);
    const float4*     myrow4 = xs4 + l * ROWF4;        // lane l's entity row
    const ulonglong2* myrow2 = (const ulonglong2*)myrow4;

    __shared__ float sp[NW][NB];
    __shared__ float sinv_s[NB];

    // ---- index width detection (int64 => high words zero) ----
    int odd  = e1w[1] | e1w[3] | e1w[5] | e1w[7] | e1w[9] | e1w[11] | e1w[13] | e1w[15];
    int is64 = (odd == 0);

    // ---- build h = norm(ent[e1[b]]) + norm(rel[rel[b]]) ----
    for (int b = w; b < NB; b += NW) {
        long long ei, ri;
        if (is64) { ei = ((const long long*)e1w)[b]; ri = ((const long long*)relw)[b]; }
        else      { ei = (long long)e1w[b];          ri = (long long)relw[b]; }
        float4 a = ((const float4*)ent)[(size_t)ei * 32 + l];
        float sa = wsum(fmaf(a.x, a.x, fmaf(a.y, a.y, fmaf(a.z, a.z, a.w * a.w))));
        float ia = rsqrtf(fmaxf(sa, 1e-24f));
        float4 c = ((const float4*)relemb)[(size_t)ri * 32 + l];
        float sc = wsum(fmaf(c.x, c.x, fmaf(c.y, c.y, fmaf(c.z, c.z, c.w * c.w))));
        float ic = rsqrtf(fmaxf(sc, 1e-24f));
        float4 h;
        h.x = fmaf(a.x, ia, c.x * ic);
        h.y = fmaf(a.y, ia, c.y * ic);
        h.z = fmaf(a.z, ia, c.z * ic);
        h.w = fmaf(a.w, ia, c.w * ic);
        ((float4*)hs)[b * 32 + l] = h;
    }
    __syncthreads();                                   // h ready; no more block syncs in loop

    float es[NB];
    #pragma unroll
    for (int b = 0; b < NB; b++) es[b] = 0.0f;

    // ---- prologue: grab + stage first tile ----
    unsigned t = 0u;
    if (l == 0) t = atomicAdd(&g_ctr, 1u);
    t = __shfl_sync(0xffffffffu, t, 0);
    if (t < (unsigned)NTILES) {
        const char* src = (const char*)ent + (size_t)t * 32 * 512 + l * 16;
        #pragma unroll
        for (int r = 0; r < 32; r++)
            cpa16(xw_u + r * (ROWF4 * 16) + l * 16, src + (size_t)r * 512);
    }
    asm volatile("cp.async.commit_group;");

    // =============== phase 1: dist -> exp -> store (no barriers) ===============
    while (t < (unsigned)NTILES) {
        int base = (int)t * 32;

        // grab next tile index while the copy is in flight
        unsigned tn = 0u;
        if (l == 0) tn = atomicAdd(&g_ctr, 1u);
        tn = __shfl_sync(0xffffffffu, tn, 0);

        asm volatile("cp.async.wait_group 0;");
        __syncwarp();

        // per-lane sumsq of own entity row (conflict-free, immediate offsets)
        float s0 = 0.f, s1 = 0.f, s2 = 0.f, s3 = 0.f;
        #pragma unroll
        for (int c = 0; c < 32; c += 4) {
            float4 v0 = myrow4[c], v1 = myrow4[c+1], v2 = myrow4[c+2], v3 = myrow4[c+3];
            s0 = fmaf(v0.x, v0.x, fmaf(v0.y, v0.y, fmaf(v0.z, v0.z, fmaf(v0.w, v0.w, s0))));
            s1 = fmaf(v1.x, v1.x, fmaf(v1.y, v1.y, fmaf(v1.z, v1.z, fmaf(v1.w, v1.w, s1))));
            s2 = fmaf(v2.x, v2.x, fmaf(v2.y, v2.y, fmaf(v2.z, v2.z, fmaf(v2.w, v2.w, s2))));
            s3 = fmaf(v3.x, v3.x, fmaf(v3.y, v3.y, fmaf(v3.z, v3.z, fmaf(v3.w, v3.w, s3))));
        }
        float ss  = (s0 + s1) + (s2 + s3);
        float inv = -rsqrtf(fmaxf(ss, 1e-24f));        // xn = -x * rsqrt(ss), on the fly
        ull nI = pk2(inv, inv);

        ull acc[NB];
        #pragma unroll
        for (int b = 0; b < NB; b++) acc[b] = 0ull;

        // 16 independent acc chains; h via single-address broadcast LDS.128
        #pragma unroll 2
        for (int c = 0; c < 32; c++) {
            ulonglong2 x = myrow2[c];                  // lane-private, conflict-free
            ull xn0 = mul2(x.x, nI);
            ull xn1 = mul2(x.y, nI);
            #pragma unroll
            for (int b = 0; b < NB; b++) {
                ulonglong2 hh = hs2[b * 32 + c];       // uniform -> broadcast (1 phase)
                acc[b] = add2(acc[b], abs2(add2(hh.x, xn0)));
                acc[b] = add2(acc[b], abs2(add2(hh.y, xn1)));
            }
        }

        // staging buffer is dead now: start staging tile tn, epilogue covers latency
        if (tn < (unsigned)NTILES) {
            const char* src = (const char*)ent + (size_t)tn * 32 * 512 + l * 16;
            #pragma unroll
            for (int r = 0; r < 32; r++)
                cpa16(xw_u + r * (ROWF4 * 16) + l * 16, src + (size_t)r * 512);
        }
        asm volatile("cp.async.commit_group;");

        // epilogue: exp + coalesced store (dist <= ~34: softmax needs no max pass)
        {
            float* outp = out + base + l;
            #pragma unroll
            for (int b = 0; b < NB; b++) {
                float2 f = upk(acc[b]);
                float e = __expf(f.x + f.y);
                outp[(size_t)b * NENT] = e;
                es[b] += e;
            }
        }
        t = tn;
    }
    asm volatile("cp.async.wait_group 0;");            // drain (last commit may be empty)

    // ---- warp -> block row sums ----
    #pragma unroll
    for (int b = 0; b < NB; b++) {
        float s = wsum(es[b]);
        if (l == 0) sp[w][b] = s;
    }
    __syncthreads();
    if (tid < NB) {
        float s = 0.f;
        #pragma unroll
        for (int ww = 0; ww < NW; ww++) s += sp[ww][tid];
        g_part[tid * GRID + blockIdx.x] = s;
    }

    // =============== grid-wide barrier (all 296 blocks co-resident) ===============
    __syncthreads();
    if (tid == 0) {
        __threadfence();
        unsigned old = atomicAdd(&g_done, 1u);
        unsigned target = (old / GRID + 1u) * GRID;
        if (old % GRID == GRID - 1u) g_ctr = 0u;       // reset queue for next replay
        unsigned d;
        do {
            asm volatile("ld.global.acquire.gpu.u32 %0, [%1];" : "=r"(d) : "l"(&g_done));
        } while (d < target);
    }
    __syncthreads();

    // ---- reduce partials -> 1/sum per row ----
    for (int b = w; b < NB; b += NW) {
        float s = 0.f;
        for (int i = l; i < GRID; i += 32) s += g_part[b * GRID + i];
        s = wsum(s);
        if (l == 0) sinv_s[b] = 1.0f / s;
    }
    __syncthreads();

    // =============== phase 2: normalize in place (L2-hot) ===============
    {
        const int total4 = NB * NENT / 4;              // 400000
        const int chunk  = (total4 + GRID - 1) / GRID; // 1352
        int start = blockIdx.x * chunk;
        int end   = min(start + chunk, total4);
        float4* o4 = (float4*)out;
        for (int i = start + tid; i < end; i += TPB) {
            int b = i / (NENT / 4);
            float iv = sinv_s[b];
            float4 v = o4[i];
            v.x *= iv; v.y *= iv; v.z *= iv; v.w *= iv;
            o4[i] = v;
        }
    }
}

// ---------------- launch ----------------
extern "C" void kernel_launch(void* const* d_in, const int* in_sizes, int n_in,
                              void* d_out, int out_size) {
    const int*   e1     = (const int*)d_in[0];
    const int*   rel    = (const int*)d_in[1];
    // d_in[2]=X, d_in[3]=A unused by the forward pass
    const float* ent    = (const float*)d_in[4];
    const float* relemb = (const float*)d_in[5];
    float* out = (float*)d_out;

    cudaFuncSetAttribute(k_fused, cudaFuncAttributeMaxDynamicSharedMemorySize, SMEM_BYTES);
    k_fused<<<GRID, TPB, SMEM_BYTES>>>(ent, relemb, e1, rel, out);
    (void)in_sizes; (void)n_in; (void)out_size;
}